// round 15
// baseline (speedup 1.0000x reference)
#include <cuda_runtime.h>
#include <cstdint>

#define NB   8
#define NA   25200
#define NC   80
#define NTOP 1000
#define NBINS 4096
#define PAIRCAP 2048

#define CBLK  256    // threads == anchors per k_conf block
#define CF4   20     // float4 per anchor (80 floats)
#define PADF4 21     // padded float4 stride (336B) -> conflict-free LDS
#define CONF_SMEM (CBLK * PADF4 * 16)

#define GRID_WAIT()  asm volatile("griddepcontrol.wait;" ::: "memory")
#define GRID_TRIG()  asm volatile("griddepcontrol.launch_dependents;" ::: "memory")

// -------------------- scratch (device globals; no allocation) --------------------
__device__ unsigned long long g_selkey[NB * NA];   // (bits(1-masked)<<32) | (anchor<<7) | cls
__device__ int                g_hist[NB * NBINS];  // zero at load; k_tail re-zeroes each replay

// -------------------- kernel 1: conf/argmax, thread-per-anchor via smem staging --------------------
__global__ __launch_bounds__(256) void k_conf(const float* __restrict__ scores) {
    extern __shared__ float4 ss[];                 // CBLK*PADF4 float4 = 86016 B
    const float4* s4 = (const float4*)scores;
    int t = threadIdx.x;
    int blockbase = blockIdx.x * CBLK;
    const int total = NB * NA;

#pragma unroll
    for (int i = 0; i < CF4; i += 5) {
        float4 v[5];
#pragma unroll
        for (int k = 0; k < 5; k++) {
            int g = (i + k) * CBLK + t;
            int anc = blockbase + g / CF4;
            v[k] = (anc < total) ? s4[(size_t)blockbase * CF4 + g]
                                 : make_float4(0.f, 0.f, 0.f, 0.f);
        }
#pragma unroll
        for (int k = 0; k < 5; k++) {
            int g = (i + k) * CBLK + t;
            ss[(g / CF4) * PADF4 + (g % CF4)] = v[k];
        }
    }
    __syncthreads();

    int anchor = blockbase + t;
    const float4* arow = ss + t * PADF4;
    unsigned long long best = 0;
#pragma unroll
    for (int q = 0; q < CF4; q++) {
        float4 w = arow[q];
        int c = 4 * q;
        unsigned long long k0 = ((unsigned long long)__float_as_uint(w.x) << 8) | (unsigned)(255 - c);
        unsigned long long k1 = ((unsigned long long)__float_as_uint(w.y) << 8) | (unsigned)(254 - c);
        unsigned long long k2 = ((unsigned long long)__float_as_uint(w.z) << 8) | (unsigned)(253 - c);
        unsigned long long k3 = ((unsigned long long)__float_as_uint(w.w) << 8) | (unsigned)(252 - c);
        unsigned long long m01 = k0 > k1 ? k0 : k1;
        unsigned long long m23 = k2 > k3 ? k2 : k3;
        unsigned long long mq  = m01 > m23 ? m01 : m23;
        if (mq > best) best = mq;
    }

    unsigned hidx = 0xFFFFFFFFu;
    if (anchor < total) {
        unsigned valbits = (unsigned)(best >> 8);
        int      cls     = 255 - (int)(best & 0xFFull);
        float conf = __uint_as_float(valbits);     // scores nonneg: uint order == float order
        float m    = (conf >= 0.5f) ? conf : -1.0f;
        float tv   = 1.0f - m;                     // exact (Sterbenz) for m in [0.5,1]
        unsigned tb = __float_as_uint(tv);
        int b = anchor / NA;
        int a = anchor - b * NA;
        g_selkey[anchor] = ((unsigned long long)tb << 32) | ((unsigned)(a << 7)) | (unsigned)cls;
        hidx = (unsigned)(b * NBINS) + (tb >> 20);
    }
    unsigned grp = __match_any_sync(0xffffffffu, hidx);
    int leader = __ffs(grp) - 1;
    if ((t & 31) == leader && hidx != 0xFFFFFFFFu)
        atomicAdd(&g_hist[hidx], __popc(grp));
    GRID_TRIG();
}

// -------------------- kernel 2: full tail, ONE working block per batch (grid padded to 148) --------------------
// smem layout (words):
#define MW_CAND  0       // ull[4096]  8192
#define MW_WSUM  8192    // int[32]
#define MW_SCAL  8224    // int[4]   [0]=s_sel [1]=chosen [2]=mm [3]=append counter
#define W_SV     8228    // float[1024]
#define W_SCL    9252    // int[1024]
#define W_STB    10276   // float4[1024]
#define W_SOB    14372   // float4[1024]
#define W_BCNT   18468   // int[128]
#define W_BPRE   18596   // int[128]
#define W_BCUR   18724   // int[128]
#define W_BMEM   18852   // int[1024]
#define W_PAIRS  19876   // int[PAIRCAP]
#define W_SPAIRS 21924   // int[PAIRCAP]
#define W_SKEEP  23972   // unsigned[32]
#define W_NP     24004   // int[1]
#define TAIL_SMEM_WORDS 24008
__global__ __launch_bounds__(1024) void k_tail(const float* __restrict__ boxes,
                                               float* __restrict__ out) {
    if (blockIdx.x >= NB) return;              // grid padded to dodge low-grid throttle

    extern __shared__ unsigned sh[];
    unsigned long long* cand = (unsigned long long*)(sh + MW_CAND);
    int*      wsum  = (int*)(sh + MW_WSUM);
    int*      scal  = (int*)(sh + MW_SCAL);
    float*    sv    = (float*)(sh + W_SV);
    int*      scl   = (int*)(sh + W_SCL);
    float4*   stb   = (float4*)(sh + W_STB);
    float4*   sob   = (float4*)(sh + W_SOB);
    int*      bcnt  = (int*)(sh + W_BCNT);
    int*      bpre  = (int*)(sh + W_BPRE);
    int*      bcur  = (int*)(sh + W_BCUR);
    int*      bmem  = (int*)(sh + W_BMEM);
    int*      pairs = (int*)(sh + W_PAIRS);
    int*      spairs= (int*)(sh + W_SPAIRS);
    unsigned* skeep = sh + W_SKEEP;
    int*      np    = (int*)(sh + W_NP);

    int b = blockIdx.x, t = threadIdx.x;
    int lane = t & 31, wid = t >> 5;

    GRID_WAIT();                               // k_conf's hist/selkey now visible

    // ---- init defaults + counters ----
    sv[t]  = -1.0f;
    scl[t] = 127;
    stb[t] = make_float4(0.f, 0.f, 0.f, 0.f);
    sob[t] = make_float4(0.f, 0.f, 0.f, 0.f);
    if (t < 128) { bcnt[t] = 0; bcur[t] = 0; }
    if (t == 0) { np[0] = 0; scal[0] = 1024; scal[3] = 0; }

    // ---- decide boundary bin ----
    int hb = b * NBINS + t * 4;
    int h0 = g_hist[hb + 0], h1 = g_hist[hb + 1], h2 = g_hist[hb + 2], h3 = g_hist[hb + 3];
    g_hist[hb + 0] = 0; g_hist[hb + 1] = 0; g_hist[hb + 2] = 0; g_hist[hb + 3] = 0;
    int local = h0 + h1 + h2 + h3;

    int v = local;
#pragma unroll
    for (int off = 1; off < 32; off <<= 1) {
        int n = __shfl_up_sync(0xffffffffu, v, off);
        if (lane >= off) v += n;
    }
    if (lane == 31) wsum[wid] = v;
    __syncthreads();
    if (t < 32) {
        int s = wsum[t];
        int is = s;
#pragma unroll
        for (int off = 1; off < 32; off <<= 1) {
            int n = __shfl_up_sync(0xffffffffu, is, off);
            if (t >= off) is += n;
        }
        wsum[t] = is - s;
    }
    __syncthreads();
    int incl = v + wsum[wid];
    int excl = incl - local;
    if (excl < NTOP && incl >= NTOP) atomicMin(&scal[0], t);
    __syncthreads();
    if (t == scal[0]) {
        int bin, mm;
        if      (excl + h0 >= NTOP)           { bin = t * 4 + 0; mm = excl + h0; }
        else if (excl + h0 + h1 >= NTOP)      { bin = t * 4 + 1; mm = excl + h0 + h1; }
        else if (excl + h0 + h1 + h2 >= NTOP) { bin = t * 4 + 2; mm = excl + h0 + h1 + h2; }
        else                                  { bin = t * 4 + 3; mm = excl + local; }
        scal[1] = bin; scal[2] = mm;
    }
    __syncthreads();
    int chosen = scal[1];
    int mm = scal[2];

    // ---- compaction: warp-aggregated single-counter append (order arbitrary) ----
    const ulonglong2* keys2 = (const ulonglong2*)(g_selkey + (size_t)b * NA);
#pragma unroll 1
    for (int base = 0; base < 12288; base += 4096) {          // 3 rounds x MLP 4
        ulonglong2 kk[4];
#pragma unroll
        for (int r = 0; r < 4; r++) kk[r] = keys2[base + r * 1024 + t];
#pragma unroll
        for (int r = 0; r < 4; r++) {
#pragma unroll
            for (int half = 0; half < 2; half++) {
                unsigned long long key = half ? kk[r].y : kk[r].x;
                bool p = ((int)(key >> 52) <= chosen);
                unsigned bal = __ballot_sync(0xffffffffu, p);
                if (bal) {
                    int cw = __popc(bal);
                    int leader = __ffs(bal) - 1;
                    int bs = 0;
                    if (lane == leader) bs = atomicAdd(&scal[3], cw);
                    bs = __shfl_sync(0xffffffffu, bs, leader);
                    if (p) {
                        int pos = bs + __popc(bal & ((1u << lane) - 1u));
                        if (pos < 4096) cand[pos] = key;
                    }
                }
            }
        }
    }
    {
        bool inb = (t < (NA / 2 - 12288));                    // remainder 312
        ulonglong2 kk = inb ? keys2[12288 + t] : make_ulonglong2(~0ull, ~0ull);
#pragma unroll
        for (int half = 0; half < 2; half++) {
            unsigned long long key = half ? kk.y : kk.x;
            bool p = inb && ((int)(key >> 52) <= chosen);
            unsigned bal = __ballot_sync(0xffffffffu, p);
            if (bal) {
                int cw = __popc(bal);
                int leader = __ffs(bal) - 1;
                int bs = 0;
                if (lane == leader) bs = atomicAdd(&scal[3], cw);
                bs = __shfl_sync(0xffffffffu, bs, leader);
                if (p) {
                    int pos = bs + __popc(bal & ((1u << lane) - 1u));
                    if (pos < 4096) cand[pos] = key;
                }
            }
        }
    }
    __syncthreads();

    // ---- bitonic sort candidates (rank == sorted index) ----
    int sortN = (mm <= 2048) ? 2048 : 4096;
    int sc = mm < 4096 ? mm : 4096;
    for (int i = sc + t; i < sortN; i += 1024) cand[i] = ~0ull;   // pad with max
    __syncthreads();
#pragma unroll 1
    for (int k = 2; k <= sortN; k <<= 1) {
#pragma unroll 1
        for (int j = k >> 1; j > 0; j >>= 1) {
#pragma unroll 1
            for (int i = t; i < sortN; i += 1024) {
                int ixj = i ^ j;
                if (ixj > i) {
                    unsigned long long a = cand[i], c2 = cand[ixj];
                    bool up = ((i & k) == 0);
                    if ((a > c2) == up) { cand[i] = c2; cand[ixj] = a; }
                }
            }
            __syncthreads();
        }
    }

    // ---- gather top-NTOP directly by sorted index ----
    const float4* bx4 = (const float4*)boxes;
    if (t < NTOP) {
        unsigned long long ke = cand[t];       // mm >= NTOP always
        int a   = (int)((unsigned)(ke & 0xFFFFFFFFull) >> 7);
        int cls = (int)(ke & 127ull);
        float tt = __uint_as_float((unsigned)(ke >> 32));
        float vv = 1.0f - tt;                  // bit-exact reconstruction of masked conf
        float cf = (float)cls;
        float4 bb = bx4[b * NA + a];
        sv[t]  = vv;
        scl[t] = cls;
        stb[t] = bb;
        float off = cf * 4096.0f;              // exact (int*pow2)
        sob[t] = make_float4(bb.x + off, bb.y + off, bb.z + off, bb.w + off);
    }
    __syncthreads();

    // ---- class buckets: count, prefix, scatter ----
    if (t < NTOP) atomicAdd(&bcnt[scl[t]], 1);
    __syncthreads();
    if (t < 32) {
        int s0 = bcnt[t * 4 + 0], s1 = bcnt[t * 4 + 1], s2 = bcnt[t * 4 + 2], s3 = bcnt[t * 4 + 3];
        int loc = s0 + s1 + s2 + s3;
        int is = loc;
#pragma unroll
        for (int off = 1; off < 32; off <<= 1) {
            int n = __shfl_up_sync(0xffffffffu, is, off);
            if (t >= off) is += n;
        }
        int base = is - loc;
        bpre[t * 4 + 0] = base;
        bpre[t * 4 + 1] = base + s0;
        bpre[t * 4 + 2] = base + s0 + s1;
        bpre[t * 4 + 3] = base + s0 + s1 + s2;
    }
    __syncthreads();
    if (t < NTOP) {
        int c = scl[t];
        bmem[bpre[c] + atomicAdd(&bcur[c], 1)] = t;   // bucket order irrelevant
    }
    __syncthreads();

    // ---- within-class IoU pairs only (cross-class inter == 0 exactly: offsets >= 4096 apart) ----
    {
#pragma unroll 1
        for (int cc = 0; cc < 4; cc++) {
            int c = wid * 4 + cc;
            int n = bcnt[c];
            int base = bpre[c];
            int npair = n * (n - 1) / 2;
            for (int p = lane; p < npair; p += 32) {
                int a = 0, rem = p;
                while (rem >= n - 1 - a) { rem -= n - 1 - a; a++; }
                int bb2 = a + 1 + rem;
                int ra = bmem[base + a], rb = bmem[base + bb2];
                int i = ra < rb ? ra : rb;
                int j = ra < rb ? rb : ra;
                float4 bi = sob[i];
                float4 bj = sob[j];
                float xx1 = fmaxf(bi.x, bj.x);
                float yy1 = fmaxf(bi.y, bj.y);
                float xx2 = fminf(bi.z, bj.z);
                float yy2 = fminf(bi.w, bj.w);
                float iw = fmaxf(xx2 - xx1, 0.0f);
                float ih = fmaxf(yy2 - yy1, 0.0f);
                float inter = iw * ih;
                float areai = (bi.z - bi.x) * (bi.w - bi.y);
                float areaj = (bj.z - bj.x) * (bj.w - bj.y);
                float u = areai + areaj - inter + 1e-7f;
                if ((inter / u) > 0.6f) {                       // exact div: match reference
                    int pos = atomicAdd(np, 1);
                    if (pos < PAIRCAP) pairs[pos] = (i << 10) | j;
                }
            }
        }
    }
    __syncthreads();

    // ---- rank-sort pairs by (i,j) ----
    int P = np[0]; if (P > PAIRCAP) P = PAIRCAP;
    for (int k = t; k < P; k += 1024) {
        int val = pairs[k];
        int rk = 0;
        for (int q = 0; q < P; q++) rk += (pairs[q] < val) ? 1 : 0;   // values unique
        spairs[rk] = val;
    }
    {
        float vv = sv[t];
        unsigned wd = __ballot_sync(0xffffffffu, vv >= 0.5f && t < NTOP);
        if (lane == 0) skeep[wid] = wd;
    }
    __syncthreads();

    // ---- serial greedy over sorted pairs (ascending i => keep[i] final when reached) ----
    if (t == 0) {
        for (int k = 0; k < P; k++) {
            int v2 = spairs[k];
            int i = v2 >> 10, j = v2 & 1023;
            if ((skeep[i >> 5] >> (i & 31)) & 1u)
                skeep[j >> 5] &= ~(1u << (j & 31));
        }
    }
    __syncthreads();

    // ---- output ----
    if (t < NTOP) {
        bool keep = (skeep[t >> 5] >> (t & 31)) & 1u;
        float vv = sv[t];
        float fk = keep ? 1.0f : 0.0f;
        float4 bb = stb[t];
        float cf = (float)scl[t];
        int o = b * NTOP + t;
        float4 o0 = make_float4(vv * fk, bb.x * fk, bb.y * fk, bb.z * fk);
        float4 o1 = make_float4(bb.w * fk, (float)b * fk, cf * fk, 0.0f);
        ((float4*)out)[o * 2 + 0] = o0;
        ((float4*)out)[o * 2 + 1] = o1;
    }
}

// -------------------- launch: 2 PDL-chained nodes, allocation-free --------------------
static void launch_pdl(const void* func, dim3 grid, dim3 block, size_t smem,
                       void** args, bool dependent) {
    cudaLaunchConfig_t cfg = {};
    cfg.gridDim = grid;
    cfg.blockDim = block;
    cfg.dynamicSmemBytes = smem;
    cfg.stream = 0;
    cudaLaunchAttribute attr[1];
    if (dependent) {
        attr[0].id = cudaLaunchAttributeProgrammaticStreamSerialization;
        attr[0].val.programmaticStreamSerializationAllowed = 1;
        cfg.attrs = attr;
        cfg.numAttrs = 1;
    }
    cudaLaunchKernelExC(&cfg, func, args);
}

extern "C" void kernel_launch(void* const* d_in, const int* in_sizes, int n_in,
                              void* d_out, int out_size) {
    const float* boxes  = (const float*)d_in[0];
    const float* scores = (const float*)d_in[1];
    if (n_in >= 2 && in_sizes[0] > in_sizes[1]) {
        const float* tmp = boxes; boxes = scores; scores = tmp;
    }
    float* out = (float*)d_out;

    cudaFuncSetAttribute(k_conf, cudaFuncAttributeMaxDynamicSharedMemorySize, CONF_SMEM);
    cudaFuncSetAttribute(k_tail, cudaFuncAttributeMaxDynamicSharedMemorySize,
                         TAIL_SMEM_WORDS * 4);

    void* a_conf[] = { (void*)&scores };
    void* a_tail[] = { (void*)&boxes, (void*)&out };

    int conf_grid = (NB * NA + CBLK - 1) / CBLK;   // 788
    launch_pdl((const void*)k_conf, dim3(conf_grid), dim3(CBLK), CONF_SMEM, a_conf, false);
    launch_pdl((const void*)k_tail, dim3(148), dim3(1024), TAIL_SMEM_WORDS * 4, a_tail, true);
    (void)out_size;
}

// round 16
// speedup vs baseline: 1.2490x; 1.2490x over previous
#include <cuda_runtime.h>
#include <cstdint>

#define NB   8
#define NA   25200
#define NC   80
#define NTOP 1000
#define NBINS 4096
#define CAP  6144
#define PAIRCAP 2048
#define T0BITS 0x3A800000u   // t < 2^-10 pre-filter threshold

#define CBLK  256    // threads == anchors per k_conf block
#define CF4   20     // float4 per anchor (80 floats)
#define PADF4 21     // padded float4 stride (336B) -> conflict-free LDS
#define CONF_SMEM (CBLK * PADF4 * 16)

#define GRID_WAIT()  asm volatile("griddepcontrol.wait;" ::: "memory")
#define GRID_TRIG()  asm volatile("griddepcontrol.launch_dependents;" ::: "memory")

// -------------------- scratch (device globals; no allocation) --------------------
__device__ unsigned long long g_selkey[NB * NA];   // (bits(1-masked)<<32) | (anchor<<7) | cls
__device__ int                g_hist[NB * NBINS];  // zero at load; k_tail re-zeroes each replay
__device__ unsigned long long g_cand[NB * CAP];    // pre-filtered candidates (t < 2^-10)
__device__ int                g_ccnt[NB];          // candidate counts (k_tail resets)

// -------------------- kernel 1: conf/argmax + candidate pre-filter --------------------
__global__ __launch_bounds__(256) void k_conf(const float* __restrict__ scores) {
    extern __shared__ float4 ss[];                 // CBLK*PADF4 float4 = 86016 B
    const float4* s4 = (const float4*)scores;
    int t = threadIdx.x;
    int blockbase = blockIdx.x * CBLK;
    const int total = NB * NA;

#pragma unroll
    for (int i = 0; i < CF4; i += 5) {
        float4 v[5];
#pragma unroll
        for (int k = 0; k < 5; k++) {
            int g = (i + k) * CBLK + t;
            int anc = blockbase + g / CF4;
            v[k] = (anc < total) ? s4[(size_t)blockbase * CF4 + g]
                                 : make_float4(0.f, 0.f, 0.f, 0.f);
        }
#pragma unroll
        for (int k = 0; k < 5; k++) {
            int g = (i + k) * CBLK + t;
            ss[(g / CF4) * PADF4 + (g % CF4)] = v[k];
        }
    }
    __syncthreads();

    int anchor = blockbase + t;
    const float4* arow = ss + t * PADF4;
    unsigned long long best = 0;
#pragma unroll
    for (int q = 0; q < CF4; q++) {
        float4 w = arow[q];
        int c = 4 * q;
        unsigned long long k0 = ((unsigned long long)__float_as_uint(w.x) << 8) | (unsigned)(255 - c);
        unsigned long long k1 = ((unsigned long long)__float_as_uint(w.y) << 8) | (unsigned)(254 - c);
        unsigned long long k2 = ((unsigned long long)__float_as_uint(w.z) << 8) | (unsigned)(253 - c);
        unsigned long long k3 = ((unsigned long long)__float_as_uint(w.w) << 8) | (unsigned)(252 - c);
        unsigned long long m01 = k0 > k1 ? k0 : k1;
        unsigned long long m23 = k2 > k3 ? k2 : k3;
        unsigned long long mq  = m01 > m23 ? m01 : m23;
        if (mq > best) best = mq;
    }

    unsigned hidx = 0xFFFFFFFFu;
    if (anchor < total) {
        unsigned valbits = (unsigned)(best >> 8);
        int      cls     = 255 - (int)(best & 0xFFull);
        float conf = __uint_as_float(valbits);     // scores nonneg: uint order == float order
        float m    = (conf >= 0.5f) ? conf : -1.0f;
        float tv   = 1.0f - m;                     // exact (Sterbenz) for m in [0.5,1]
        unsigned tb = __float_as_uint(tv);
        int b = anchor / NA;
        int a = anchor - b * NA;
        unsigned long long key = ((unsigned long long)tb << 32) | ((unsigned)(a << 7)) | (unsigned)cls;
        g_selkey[anchor] = key;                    // kept for exact fallback path
        hidx = (unsigned)(b * NBINS) + (tb >> 20);
        if (tb < T0BITS) {                         // pre-filter: top-NTOP provably inside when M>=NTOP
            int pos = atomicAdd(&g_ccnt[b], 1);
            if (pos < CAP) g_cand[b * CAP + pos] = key;
        }
    }
    unsigned grp = __match_any_sync(0xffffffffu, hidx);
    int leader = __ffs(grp) - 1;
    if ((t & 31) == leader && hidx != 0xFFFFFFFFu)
        atomicAdd(&g_hist[hidx], __popc(grp));
    GRID_TRIG();
}

// -------------------- kernel 2: tail, ONE working block per batch (grid padded to 148) --------------------
// smem layout (words):
#define W_CAND2  0       // ull[CAP] 12288
#define W_PRE    12288   // int[4096]
#define W_CNT    16384   // int[4096]
#define W_CUR    20480   // int[4096]
#define W_WSUM   24576   // int[32]
#define W_SCAL   24608   // int[4]
#define W_SV     24612   // float[1024]
#define W_SCL    25636   // int[1024]
#define W_STB    26660   // float4[1024]
#define W_SOB    30756   // float4[1024]
#define W_BCNT   34852   // int[128]
#define W_BPRE   34980   // int[128]
#define W_BCUR   35108   // int[128]
#define W_BMEM   35236   // int[1024]
#define W_PAIRS  36260   // int[PAIRCAP]
#define W_SPAIRS 38308   // int[PAIRCAP]
#define W_SKEEP  40356   // unsigned[32]
#define W_NP     40388   // int[1]
#define TAIL_SMEM_WORDS 40392
__global__ __launch_bounds__(1024) void k_tail(const float* __restrict__ boxes,
                                               float* __restrict__ out) {
    if (blockIdx.x >= NB) return;              // grid padded to dodge low-grid throttle

    extern __shared__ unsigned sh[];
    unsigned long long* cand2 = (unsigned long long*)(sh + W_CAND2);
    int*      pre   = (int*)(sh + W_PRE);
    int*      cnt   = (int*)(sh + W_CNT);
    int*      cur   = (int*)(sh + W_CUR);
    int*      wsum  = (int*)(sh + W_WSUM);
    int*      scal  = (int*)(sh + W_SCAL);
    float*    sv    = (float*)(sh + W_SV);
    int*      scl   = (int*)(sh + W_SCL);
    float4*   stb   = (float4*)(sh + W_STB);
    float4*   sob   = (float4*)(sh + W_SOB);
    int*      bcnt  = (int*)(sh + W_BCNT);
    int*      bpre  = (int*)(sh + W_BPRE);
    int*      bcur  = (int*)(sh + W_BCUR);
    int*      bmem  = (int*)(sh + W_BMEM);
    int*      pairs = (int*)(sh + W_PAIRS);
    int*      spairs= (int*)(sh + W_SPAIRS);
    unsigned* skeep = sh + W_SKEEP;
    int*      np    = (int*)(sh + W_NP);

    int b = blockIdx.x, t = threadIdx.x;
    int lane = t & 31, wid = t >> 5;

    GRID_WAIT();                               // k_conf's cand/hist/selkey now visible

    // ---- init defaults + counters ----
    sv[t]  = -1.0f;
    scl[t] = 127;
    stb[t] = make_float4(0.f, 0.f, 0.f, 0.f);
    sob[t] = make_float4(0.f, 0.f, 0.f, 0.f);
    if (t < 128) { bcnt[t] = 0; bcur[t] = 0; }
    if (t == 0) { np[0] = 0; scal[0] = 1024; }
    cnt[t * 4 + 0] = 0; cnt[t * 4 + 1] = 0; cnt[t * 4 + 2] = 0; cnt[t * 4 + 3] = 0;
    cur[t * 4 + 0] = 0; cur[t * 4 + 1] = 0; cur[t * 4 + 2] = 0; cur[t * 4 + 3] = 0;

    // read + zero histogram (needed by fallback; zeroed for next replay either way)
    int hb = b * NBINS + t * 4;
    int h0 = g_hist[hb + 0], h1 = g_hist[hb + 1], h2 = g_hist[hb + 2], h3 = g_hist[hb + 3];
    g_hist[hb + 0] = 0; g_hist[hb + 1] = 0; g_hist[hb + 2] = 0; g_hist[hb + 3] = 0;

    int M = g_ccnt[b];
    if (t == 0) g_ccnt[b] = 0;                 // reset for next replay
    bool fast = (M >= NTOP && M <= CAP);
    __syncthreads();

    if (fast) {
        // ===== FAST PATH: histogram + scatter + rank over M (~1900) candidates =====
        const unsigned long long* gc = g_cand + (size_t)b * CAP;
        for (int i = t; i < M; i += 1024)
            atomicAdd(&cnt[(int)(gc[i] >> 52)], 1);
        __syncthreads();
        // prefix over 4096 bins
        int c0 = cnt[t * 4 + 0], c1 = cnt[t * 4 + 1], c2 = cnt[t * 4 + 2], c3 = cnt[t * 4 + 3];
        int local = c0 + c1 + c2 + c3;
        int v = local;
#pragma unroll
        for (int off = 1; off < 32; off <<= 1) {
            int n = __shfl_up_sync(0xffffffffu, v, off);
            if (lane >= off) v += n;
        }
        if (lane == 31) wsum[wid] = v;
        __syncthreads();
        if (t < 32) {
            int s = wsum[t];
            int is = s;
#pragma unroll
            for (int off = 1; off < 32; off <<= 1) {
                int n = __shfl_up_sync(0xffffffffu, is, off);
                if (t >= off) is += n;
            }
            wsum[t] = is - s;
        }
        __syncthreads();
        int excl = (v + wsum[wid]) - local;
        pre[t * 4 + 0] = excl;
        pre[t * 4 + 1] = excl + c0;
        pre[t * 4 + 2] = excl + c0 + c1;
        pre[t * 4 + 3] = excl + c0 + c1 + c2;
        __syncthreads();
        // scatter bin-grouped
        for (int i = t; i < M; i += 1024) {
            unsigned long long k = gc[i];
            int bin = (int)(k >> 52);
            cand2[pre[bin] + atomicAdd(&cur[bin], 1)] = k;
        }
        __syncthreads();
        // rank within own bin + gather
        const float4* bx4 = (const float4*)boxes;
        for (int e = t; e < M; e += 1024) {
            unsigned long long ke = cand2[e];
            int bin = (int)(ke >> 52);
            int start = pre[bin];
            int end   = start + cnt[bin];
            int rank  = start;
            for (int j = start; j < end; j++) rank += (cand2[j] < ke) ? 1 : 0;
            if (rank < NTOP) {
                int a   = (int)((unsigned)(ke & 0xFFFFFFFFull) >> 7);
                int cls = (int)(ke & 127ull);
                float tt = __uint_as_float((unsigned)(ke >> 32));
                float vv = 1.0f - tt;            // bit-exact reconstruction of masked conf
                float cf = (float)cls;
                float4 bb = bx4[b * NA + a];
                sv[rank]  = vv;
                scl[rank] = cls;
                stb[rank] = bb;
                float off = cf * 4096.0f;        // exact (int*pow2)
                sob[rank] = make_float4(bb.x + off, bb.y + off, bb.z + off, bb.w + off);
            }
        }
    } else {
        // ===== FALLBACK (exact, any input): histogram-bounded full scan (round-14 logic) =====
        int local = h0 + h1 + h2 + h3;
        int v = local;
#pragma unroll
        for (int off = 1; off < 32; off <<= 1) {
            int n = __shfl_up_sync(0xffffffffu, v, off);
            if (lane >= off) v += n;
        }
        if (lane == 31) wsum[wid] = v;
        __syncthreads();
        if (t < 32) {
            int s = wsum[t];
            int is = s;
#pragma unroll
            for (int off = 1; off < 32; off <<= 1) {
                int n = __shfl_up_sync(0xffffffffu, is, off);
                if (t >= off) is += n;
            }
            wsum[t] = is - s;
        }
        __syncthreads();
        int incl = v + wsum[wid];
        int excl = incl - local;
        pre[t * 4 + 0] = excl;
        pre[t * 4 + 1] = excl + h0;
        pre[t * 4 + 2] = excl + h0 + h1;
        pre[t * 4 + 3] = excl + h0 + h1 + h2;
        if (excl < NTOP && incl >= NTOP) atomicMin(&scal[0], t);
        __syncthreads();
        if (t == scal[0]) {
            int bin, mm;
            if      (excl + h0 >= NTOP)           { bin = t * 4 + 0; mm = excl + h0; }
            else if (excl + h0 + h1 >= NTOP)      { bin = t * 4 + 1; mm = excl + h0 + h1; }
            else if (excl + h0 + h1 + h2 >= NTOP) { bin = t * 4 + 2; mm = excl + h0 + h1 + h2; }
            else                                  { bin = t * 4 + 3; mm = excl + local; }
            scal[1] = bin; scal[2] = mm;
        }
        __syncthreads();
        int chosen = scal[1];
        int mm = scal[2]; if (mm > CAP) mm = CAP;
        const unsigned long long* keys = g_selkey + (size_t)b * NA;
        for (int i = t; i < NA; i += 1024) {
            unsigned long long key = keys[i];
            int bin = (int)(key >> 52);
            if (bin <= chosen) {
                int pos = pre[bin] + atomicAdd(&cur[bin], 1);
                if (pos < CAP) cand2[pos] = key;
            }
        }
        __syncthreads();
        const float4* bx4 = (const float4*)boxes;
        for (int e = t; e < mm; e += 1024) {
            unsigned long long ke = cand2[e];
            int bin = (int)(ke >> 52);
            int start = pre[bin];
            int end   = start + cur[bin]; if (end > mm) end = mm;
            int rank  = start;
            for (int j = start; j < end; j++) rank += (cand2[j] < ke) ? 1 : 0;
            if (rank < NTOP) {
                int a   = (int)((unsigned)(ke & 0xFFFFFFFFull) >> 7);
                int cls = (int)(ke & 127ull);
                float tt = __uint_as_float((unsigned)(ke >> 32));
                float vv = 1.0f - tt;
                float cf = (float)cls;
                float4 bb = bx4[b * NA + a];
                sv[rank]  = vv;
                scl[rank] = cls;
                stb[rank] = bb;
                float off = cf * 4096.0f;
                sob[rank] = make_float4(bb.x + off, bb.y + off, bb.z + off, bb.w + off);
            }
        }
    }
    __syncthreads();

    // ---- class buckets: count, prefix, scatter ----
    if (t < NTOP) atomicAdd(&bcnt[scl[t]], 1);
    __syncthreads();
    if (t < 32) {
        int s0 = bcnt[t * 4 + 0], s1 = bcnt[t * 4 + 1], s2 = bcnt[t * 4 + 2], s3 = bcnt[t * 4 + 3];
        int loc = s0 + s1 + s2 + s3;
        int is = loc;
#pragma unroll
        for (int off = 1; off < 32; off <<= 1) {
            int n = __shfl_up_sync(0xffffffffu, is, off);
            if (t >= off) is += n;
        }
        int base = is - loc;
        bpre[t * 4 + 0] = base;
        bpre[t * 4 + 1] = base + s0;
        bpre[t * 4 + 2] = base + s0 + s1;
        bpre[t * 4 + 3] = base + s0 + s1 + s2;
    }
    __syncthreads();
    if (t < NTOP) {
        int c = scl[t];
        bmem[bpre[c] + atomicAdd(&bcur[c], 1)] = t;   // bucket order irrelevant
    }
    __syncthreads();

    // ---- within-class IoU pairs only (cross-class inter == 0 exactly: offsets >= 4096 apart) ----
    {
#pragma unroll 1
        for (int cc = 0; cc < 4; cc++) {
            int c = wid * 4 + cc;
            int n = bcnt[c];
            int base = bpre[c];
            int npair = n * (n - 1) / 2;
            for (int p = lane; p < npair; p += 32) {
                int a = 0, rem = p;
                while (rem >= n - 1 - a) { rem -= n - 1 - a; a++; }
                int bb2 = a + 1 + rem;
                int ra = bmem[base + a], rb = bmem[base + bb2];
                int i = ra < rb ? ra : rb;
                int j = ra < rb ? rb : ra;
                float4 bi = sob[i];
                float4 bj = sob[j];
                float xx1 = fmaxf(bi.x, bj.x);
                float yy1 = fmaxf(bi.y, bj.y);
                float xx2 = fminf(bi.z, bj.z);
                float yy2 = fminf(bi.w, bj.w);
                float iw = fmaxf(xx2 - xx1, 0.0f);
                float ih = fmaxf(yy2 - yy1, 0.0f);
                float inter = iw * ih;
                float areai = (bi.z - bi.x) * (bi.w - bi.y);
                float areaj = (bj.z - bj.x) * (bj.w - bj.y);
                float u = areai + areaj - inter + 1e-7f;
                if ((inter / u) > 0.6f) {                       // exact div: match reference
                    int pos = atomicAdd(np, 1);
                    if (pos < PAIRCAP) pairs[pos] = (i << 10) | j;
                }
            }
        }
    }
    __syncthreads();

    // ---- rank-sort pairs by (i,j) ----
    int P = np[0]; if (P > PAIRCAP) P = PAIRCAP;
    for (int k = t; k < P; k += 1024) {
        int val = pairs[k];
        int rk = 0;
        for (int q = 0; q < P; q++) rk += (pairs[q] < val) ? 1 : 0;   // values unique
        spairs[rk] = val;
    }
    {
        float vv = sv[t];
        unsigned wd = __ballot_sync(0xffffffffu, vv >= 0.5f && t < NTOP);
        if (lane == 0) skeep[wid] = wd;
    }
    __syncthreads();

    // ---- serial greedy over sorted pairs (ascending i => keep[i] final when reached) ----
    if (t == 0) {
        for (int k = 0; k < P; k++) {
            int v2 = spairs[k];
            int i = v2 >> 10, j = v2 & 1023;
            if ((skeep[i >> 5] >> (i & 31)) & 1u)
                skeep[j >> 5] &= ~(1u << (j & 31));
        }
    }
    __syncthreads();

    // ---- output ----
    if (t < NTOP) {
        bool keep = (skeep[t >> 5] >> (t & 31)) & 1u;
        float vv = sv[t];
        float fk = keep ? 1.0f : 0.0f;
        float4 bb = stb[t];
        float cf = (float)scl[t];
        int o = b * NTOP + t;
        float4 o0 = make_float4(vv * fk, bb.x * fk, bb.y * fk, bb.z * fk);
        float4 o1 = make_float4(bb.w * fk, (float)b * fk, cf * fk, 0.0f);
        ((float4*)out)[o * 2 + 0] = o0;
        ((float4*)out)[o * 2 + 1] = o1;
    }
}

// -------------------- launch: 2 PDL-chained nodes, allocation-free --------------------
static void launch_pdl(const void* func, dim3 grid, dim3 block, size_t smem,
                       void** args, bool dependent) {
    cudaLaunchConfig_t cfg = {};
    cfg.gridDim = grid;
    cfg.blockDim = block;
    cfg.dynamicSmemBytes = smem;
    cfg.stream = 0;
    cudaLaunchAttribute attr[1];
    if (dependent) {
        attr[0].id = cudaLaunchAttributeProgrammaticStreamSerialization;
        attr[0].val.programmaticStreamSerializationAllowed = 1;
        cfg.attrs = attr;
        cfg.numAttrs = 1;
    }
    cudaLaunchKernelExC(&cfg, func, args);
}

extern "C" void kernel_launch(void* const* d_in, const int* in_sizes, int n_in,
                              void* d_out, int out_size) {
    const float* boxes  = (const float*)d_in[0];
    const float* scores = (const float*)d_in[1];
    if (n_in >= 2 && in_sizes[0] > in_sizes[1]) {
        const float* tmp = boxes; boxes = scores; scores = tmp;
    }
    float* out = (float*)d_out;

    cudaFuncSetAttribute(k_conf, cudaFuncAttributeMaxDynamicSharedMemorySize, CONF_SMEM);
    cudaFuncSetAttribute(k_tail, cudaFuncAttributeMaxDynamicSharedMemorySize,
                         TAIL_SMEM_WORDS * 4);

    void* a_conf[] = { (void*)&scores };
    void* a_tail[] = { (void*)&boxes, (void*)&out };

    int conf_grid = (NB * NA + CBLK - 1) / CBLK;   // 788
    launch_pdl((const void*)k_conf, dim3(conf_grid), dim3(CBLK), CONF_SMEM, a_conf, false);
    launch_pdl((const void*)k_tail, dim3(148), dim3(1024), TAIL_SMEM_WORDS * 4, a_tail, true);
    (void)out_size;
}

// round 17
// speedup vs baseline: 1.4565x; 1.1661x over previous
#include <cuda_runtime.h>
#include <cstdint>

#define NB   8
#define NA   25200
#define NC   80
#define NTOP 1000
#define NBINS 4096
#define CAP  6144
#define PAIRCAP 2048

#define CBLK  256    // threads == anchors per k_conf block
#define CF4   20     // float4 per anchor (80 floats)
#define PADF4 21     // padded float4 stride (336B) -> conflict-free LDS
#define CONF_SMEM (CBLK * PADF4 * 16)

#define GRID_WAIT()  asm volatile("griddepcontrol.wait;" ::: "memory")
#define GRID_TRIG()  asm volatile("griddepcontrol.launch_dependents;" ::: "memory")

// bin function: 6 low exponent bits + 6 mantissa bits of tb. Monotone over the
// occupied range (t in [2^-24, 0.5] -> exps 103..126 -> high-6 = 38..62), masked
// t=2.0 (tb=0x40000000) pinned to last bin. 8x finer mantissa resolution than
// tb>>20 -> boundary bin ~125 keys instead of ~1000.
__device__ __forceinline__ int tb_bin(unsigned tb) {
    return (tb >= 0x40000000u) ? 4095 : (int)((tb >> 17) & 0xFFFu);
}

// -------------------- scratch (device globals; no allocation) --------------------
__device__ unsigned long long g_selkey[NB * NA];   // (bits(1-masked)<<32) | (anchor<<7) | cls
__device__ int                g_hist[NB * NBINS];  // zero at load; k_tail re-zeroes each replay

// -------------------- kernel 1: conf/argmax, thread-per-anchor via smem staging --------------------
__global__ __launch_bounds__(256) void k_conf(const float* __restrict__ scores) {
    extern __shared__ float4 ss[];                 // CBLK*PADF4 float4 = 86016 B
    const float4* s4 = (const float4*)scores;
    int t = threadIdx.x;
    int blockbase = blockIdx.x * CBLK;
    const int total = NB * NA;

#pragma unroll
    for (int i = 0; i < CF4; i += 5) {
        float4 v[5];
#pragma unroll
        for (int k = 0; k < 5; k++) {
            int g = (i + k) * CBLK + t;
            int anc = blockbase + g / CF4;
            v[k] = (anc < total) ? s4[(size_t)blockbase * CF4 + g]
                                 : make_float4(0.f, 0.f, 0.f, 0.f);
        }
#pragma unroll
        for (int k = 0; k < 5; k++) {
            int g = (i + k) * CBLK + t;
            ss[(g / CF4) * PADF4 + (g % CF4)] = v[k];
        }
    }
    __syncthreads();

    int anchor = blockbase + t;
    const float4* arow = ss + t * PADF4;
    unsigned long long best = 0;
#pragma unroll
    for (int q = 0; q < CF4; q++) {
        float4 w = arow[q];
        int c = 4 * q;
        unsigned long long k0 = ((unsigned long long)__float_as_uint(w.x) << 8) | (unsigned)(255 - c);
        unsigned long long k1 = ((unsigned long long)__float_as_uint(w.y) << 8) | (unsigned)(254 - c);
        unsigned long long k2 = ((unsigned long long)__float_as_uint(w.z) << 8) | (unsigned)(253 - c);
        unsigned long long k3 = ((unsigned long long)__float_as_uint(w.w) << 8) | (unsigned)(252 - c);
        unsigned long long m01 = k0 > k1 ? k0 : k1;
        unsigned long long m23 = k2 > k3 ? k2 : k3;
        unsigned long long mq  = m01 > m23 ? m01 : m23;
        if (mq > best) best = mq;
    }

    unsigned hidx = 0xFFFFFFFFu;
    if (anchor < total) {
        unsigned valbits = (unsigned)(best >> 8);
        int      cls     = 255 - (int)(best & 0xFFull);
        float conf = __uint_as_float(valbits);     // scores nonneg: uint order == float order
        float m    = (conf >= 0.5f) ? conf : -1.0f;
        float tv   = 1.0f - m;                     // exact (Sterbenz) for m in [0.5,1]
        unsigned tb = __float_as_uint(tv);
        int b = anchor / NA;
        int a = anchor - b * NA;
        g_selkey[anchor] = ((unsigned long long)tb << 32) | ((unsigned)(a << 7)) | (unsigned)cls;
        hidx = (unsigned)(b * NBINS) + (unsigned)tb_bin(tb);
    }
    unsigned grp = __match_any_sync(0xffffffffu, hidx);
    int leader = __ffs(grp) - 1;
    if ((t & 31) == leader && hidx != 0xFFFFFFFFu)
        atomicAdd(&g_hist[hidx], __popc(grp));
    GRID_TRIG();
}

// -------------------- kernel 2: full tail, ONE working block per batch (grid padded to 148) --------------------
// smem layout (words):
#define MW_CAND  0       // ull[CAP]            12288
#define MW_PRE   12288   // int[4096]
#define MW_CNT   16384   // int[4096]
#define MW_WSUM  20480   // int[32]
#define MW_SCAL  20512   // int[4]
#define W_SV     20516   // float[1024]
#define W_SCL    21540   // int[1024]
#define W_STB    22564   // float4[1024]
#define W_SOB    26660   // float4[1024]
#define W_BCNT   30756   // int[128]
#define W_BPRE   30884   // int[128]
#define W_BCUR   31012   // int[128]
#define W_BMEM   31140   // int[1024]
#define W_PAIRS  32164   // int[PAIRCAP]
#define W_SPAIRS 34212   // int[PAIRCAP]
#define W_SKEEP  36260   // unsigned[32]
#define W_NP     36292   // int[1]
#define TAIL_SMEM_WORDS 36296
__global__ __launch_bounds__(1024) void k_tail(const float* __restrict__ boxes,
                                               float* __restrict__ out) {
    if (blockIdx.x >= NB) return;              // grid padded to dodge low-grid throttle

    extern __shared__ unsigned sh[];
    unsigned long long* cand = (unsigned long long*)(sh + MW_CAND);
    int*      pre   = (int*)(sh + MW_PRE);
    int*      cnt   = (int*)(sh + MW_CNT);
    int*      wsum  = (int*)(sh + MW_WSUM);
    int*      scal  = (int*)(sh + MW_SCAL);
    float*    sv    = (float*)(sh + W_SV);
    int*      scl   = (int*)(sh + W_SCL);
    float4*   stb   = (float4*)(sh + W_STB);
    float4*   sob   = (float4*)(sh + W_SOB);
    int*      bcnt  = (int*)(sh + W_BCNT);
    int*      bpre  = (int*)(sh + W_BPRE);
    int*      bcur  = (int*)(sh + W_BCUR);
    int*      bmem  = (int*)(sh + W_BMEM);
    int*      pairs = (int*)(sh + W_PAIRS);
    int*      spairs= (int*)(sh + W_SPAIRS);
    unsigned* skeep = sh + W_SKEEP;
    int*      np    = (int*)(sh + W_NP);

    int b = blockIdx.x, t = threadIdx.x;
    int lane = t & 31, wid = t >> 5;

    GRID_WAIT();                               // k_conf's hist/selkey now visible

    // ---- init rank-array defaults + bucket counters ----
    sv[t]  = -1.0f;
    scl[t] = 127;
    stb[t] = make_float4(0.f, 0.f, 0.f, 0.f);
    sob[t] = make_float4(0.f, 0.f, 0.f, 0.f);
    if (t < 128) { bcnt[t] = 0; bcur[t] = 0; }
    if (t == 0) np[0] = 0;

    // ---- mega: decide boundary bin ----
    int hb = b * NBINS + t * 4;
    int h0 = g_hist[hb + 0], h1 = g_hist[hb + 1], h2 = g_hist[hb + 2], h3 = g_hist[hb + 3];
    g_hist[hb + 0] = 0; g_hist[hb + 1] = 0; g_hist[hb + 2] = 0; g_hist[hb + 3] = 0;
    int local = h0 + h1 + h2 + h3;

    int v = local;
#pragma unroll
    for (int off = 1; off < 32; off <<= 1) {
        int n = __shfl_up_sync(0xffffffffu, v, off);
        if (lane >= off) v += n;
    }
    if (lane == 31) wsum[wid] = v;
    if (t == 0) scal[0] = 1024;
    __syncthreads();
    if (t < 32) {
        int s = wsum[t];
        int is = s;
#pragma unroll
        for (int off = 1; off < 32; off <<= 1) {
            int n = __shfl_up_sync(0xffffffffu, is, off);
            if (t >= off) is += n;
        }
        wsum[t] = is - s;
    }
    __syncthreads();
    int incl = v + wsum[wid];
    int excl = incl - local;
    pre[t * 4 + 0] = excl;
    pre[t * 4 + 1] = excl + h0;
    pre[t * 4 + 2] = excl + h0 + h1;
    pre[t * 4 + 3] = excl + h0 + h1 + h2;
    cnt[t * 4 + 0] = 0; cnt[t * 4 + 1] = 0; cnt[t * 4 + 2] = 0; cnt[t * 4 + 3] = 0;
    if (excl < NTOP && incl >= NTOP) atomicMin(&scal[0], t);
    __syncthreads();
    if (t == scal[0]) {
        int bin, mm;
        if      (excl + h0 >= NTOP)           { bin = t * 4 + 0; mm = excl + h0; }
        else if (excl + h0 + h1 >= NTOP)      { bin = t * 4 + 1; mm = excl + h0 + h1; }
        else if (excl + h0 + h1 + h2 >= NTOP) { bin = t * 4 + 2; mm = excl + h0 + h1 + h2; }
        else                                  { bin = t * 4 + 3; mm = excl + local; }
        scal[1] = bin; scal[2] = mm;
    }
    __syncthreads();
    int chosen = scal[1];
    int m = scal[2]; if (m > CAP) m = CAP;

    // ---- mega: bin-grouped compaction, MLP=4 front-batched rounds ----
    const ulonglong2* keys2 = (const ulonglong2*)(g_selkey + (size_t)b * NA);
    for (int base = 0; base < 12288; base += 4096) {          // 3 rounds x 4 loads
        ulonglong2 kk[4];
#pragma unroll
        for (int r = 0; r < 4; r++) kk[r] = keys2[base + r * 1024 + t];
#pragma unroll
        for (int r = 0; r < 4; r++) {
            int bin0 = tb_bin((unsigned)(kk[r].x >> 32));
            if (bin0 <= chosen) {
                int pos = pre[bin0] + atomicAdd(&cnt[bin0], 1);
                if (pos < CAP) cand[pos] = kk[r].x;
            }
            int bin1 = tb_bin((unsigned)(kk[r].y >> 32));
            if (bin1 <= chosen) {
                int pos = pre[bin1] + atomicAdd(&cnt[bin1], 1);
                if (pos < CAP) cand[pos] = kk[r].y;
            }
        }
    }
    if (t < (NA / 2 - 12288)) {                                // remainder 312
        ulonglong2 kk = keys2[12288 + t];
        int bin0 = tb_bin((unsigned)(kk.x >> 32));
        if (bin0 <= chosen) {
            int pos = pre[bin0] + atomicAdd(&cnt[bin0], 1);
            if (pos < CAP) cand[pos] = kk.x;
        }
        int bin1 = tb_bin((unsigned)(kk.y >> 32));
        if (bin1 <= chosen) {
            int pos = pre[bin1] + atomicAdd(&cnt[bin1], 1);
            if (pos < CAP) cand[pos] = kk.y;
        }
    }
    __syncthreads();

    // ---- mega: per-bin rank + gather into smem (boundary bin now ~125 keys) ----
    const float4* bx4 = (const float4*)boxes;
    for (int e = t; e < m; e += 1024) {
        unsigned long long ke = cand[e];
        int bin = tb_bin((unsigned)(ke >> 32));
        int start = pre[bin];
        int end   = start + cnt[bin]; if (end > m) end = m;
        int rank  = start;
        for (int j = start; j < end; j++) rank += (cand[j] < ke) ? 1 : 0;
        if (rank < NTOP) {
            int a   = (int)((unsigned)(ke & 0xFFFFFFFFull) >> 7);
            int cls = (int)(ke & 127ull);
            float tt = __uint_as_float((unsigned)(ke >> 32));
            float vv = 1.0f - tt;                // bit-exact reconstruction of masked conf
            float cf = (float)cls;
            float4 bb = bx4[b * NA + a];
            sv[rank]  = vv;
            scl[rank] = cls;
            stb[rank] = bb;
            float off = cf * 4096.0f;            // exact (int*pow2)
            sob[rank] = make_float4(bb.x + off, bb.y + off, bb.z + off, bb.w + off);
        }
    }
    __syncthreads();

    // ---- class buckets: count, prefix, scatter ----
    if (t < NTOP) atomicAdd(&bcnt[scl[t]], 1);
    __syncthreads();
    if (t < 32) {
        int s0 = bcnt[t * 4 + 0], s1 = bcnt[t * 4 + 1], s2 = bcnt[t * 4 + 2], s3 = bcnt[t * 4 + 3];
        int loc = s0 + s1 + s2 + s3;
        int is = loc;
#pragma unroll
        for (int off = 1; off < 32; off <<= 1) {
            int n = __shfl_up_sync(0xffffffffu, is, off);
            if (t >= off) is += n;
        }
        int base = is - loc;
        bpre[t * 4 + 0] = base;
        bpre[t * 4 + 1] = base + s0;
        bpre[t * 4 + 2] = base + s0 + s1;
        bpre[t * 4 + 3] = base + s0 + s1 + s2;
    }
    __syncthreads();
    if (t < NTOP) {
        int c = scl[t];
        bmem[bpre[c] + atomicAdd(&bcur[c], 1)] = t;   // bucket order irrelevant
    }
    __syncthreads();

    // ---- within-class IoU pairs only (cross-class inter == 0 exactly: offsets >= 4096 apart) ----
    {
#pragma unroll 1
        for (int cc = 0; cc < 4; cc++) {
            int c = wid * 4 + cc;
            int n = bcnt[c];
            int base = bpre[c];
            int npair = n * (n - 1) / 2;
            for (int p = lane; p < npair; p += 32) {
                int a = 0, rem = p;
                while (rem >= n - 1 - a) { rem -= n - 1 - a; a++; }
                int bb2 = a + 1 + rem;
                int ra = bmem[base + a], rb = bmem[base + bb2];
                int i = ra < rb ? ra : rb;
                int j = ra < rb ? rb : ra;
                float4 bi = sob[i];
                float4 bj = sob[j];
                float xx1 = fmaxf(bi.x, bj.x);
                float yy1 = fmaxf(bi.y, bj.y);
                float xx2 = fminf(bi.z, bj.z);
                float yy2 = fminf(bi.w, bj.w);
                float iw = fmaxf(xx2 - xx1, 0.0f);
                float ih = fmaxf(yy2 - yy1, 0.0f);
                float inter = iw * ih;
                float areai = (bi.z - bi.x) * (bi.w - bi.y);
                float areaj = (bj.z - bj.x) * (bj.w - bj.y);
                float u = areai + areaj - inter + 1e-7f;
                if ((inter / u) > 0.6f) {                       // exact div: match reference
                    int pos = atomicAdd(np, 1);
                    if (pos < PAIRCAP) pairs[pos] = (i << 10) | j;
                }
            }
        }
    }
    __syncthreads();

    // ---- rank-sort pairs by (i,j) ----
    int P = np[0]; if (P > PAIRCAP) P = PAIRCAP;
    for (int k = t; k < P; k += 1024) {
        int val = pairs[k];
        int rk = 0;
        for (int q = 0; q < P; q++) rk += (pairs[q] < val) ? 1 : 0;   // values unique
        spairs[rk] = val;
    }
    {
        float vv = sv[t];
        unsigned wd = __ballot_sync(0xffffffffu, vv >= 0.5f && t < NTOP);
        if (lane == 0) skeep[wid] = wd;
    }
    __syncthreads();

    // ---- serial greedy over sorted pairs (ascending i => keep[i] final when reached) ----
    if (t == 0) {
        for (int k = 0; k < P; k++) {
            int v2 = spairs[k];
            int i = v2 >> 10, j = v2 & 1023;
            if ((skeep[i >> 5] >> (i & 31)) & 1u)
                skeep[j >> 5] &= ~(1u << (j & 31));
        }
    }
    __syncthreads();

    // ---- output ----
    if (t < NTOP) {
        bool keep = (skeep[t >> 5] >> (t & 31)) & 1u;
        float vv = sv[t];
        float fk = keep ? 1.0f : 0.0f;
        float4 bb = stb[t];
        float cf = (float)scl[t];
        int o = b * NTOP + t;
        float4 o0 = make_float4(vv * fk, bb.x * fk, bb.y * fk, bb.z * fk);
        float4 o1 = make_float4(bb.w * fk, (float)b * fk, cf * fk, 0.0f);
        ((float4*)out)[o * 2 + 0] = o0;
        ((float4*)out)[o * 2 + 1] = o1;
    }
}

// -------------------- launch: 2 PDL-chained nodes, allocation-free --------------------
static void launch_pdl(const void* func, dim3 grid, dim3 block, size_t smem,
                       void** args, bool dependent) {
    cudaLaunchConfig_t cfg = {};
    cfg.gridDim = grid;
    cfg.blockDim = block;
    cfg.dynamicSmemBytes = smem;
    cfg.stream = 0;
    cudaLaunchAttribute attr[1];
    if (dependent) {
        attr[0].id = cudaLaunchAttributeProgrammaticStreamSerialization;
        attr[0].val.programmaticStreamSerializationAllowed = 1;
        cfg.attrs = attr;
        cfg.numAttrs = 1;
    }
    cudaLaunchKernelExC(&cfg, func, args);
}

extern "C" void kernel_launch(void* const* d_in, const int* in_sizes, int n_in,
                              void* d_out, int out_size) {
    const float* boxes  = (const float*)d_in[0];
    const float* scores = (const float*)d_in[1];
    if (n_in >= 2 && in_sizes[0] > in_sizes[1]) {
        const float* tmp = boxes; boxes = scores; scores = tmp;
    }
    float* out = (float*)d_out;

    cudaFuncSetAttribute(k_conf, cudaFuncAttributeMaxDynamicSharedMemorySize, CONF_SMEM);
    cudaFuncSetAttribute(k_tail, cudaFuncAttributeMaxDynamicSharedMemorySize,
                         TAIL_SMEM_WORDS * 4);

    void* a_conf[] = { (void*)&scores };
    void* a_tail[] = { (void*)&boxes, (void*)&out };

    int conf_grid = (NB * NA + CBLK - 1) / CBLK;   // 788
    launch_pdl((const void*)k_conf, dim3(conf_grid), dim3(CBLK), CONF_SMEM, a_conf, false);
    launch_pdl((const void*)k_tail, dim3(148), dim3(1024), TAIL_SMEM_WORDS * 4, a_tail, true);
    (void)out_size;
}